// round 10
// baseline (speedup 1.0000x reference)
#include <cuda_runtime.h>
#include <cuda_bf16.h>
#include <math.h>
#include <float.h>
#include <stdint.h>

// Problem constants
#define HEADS   2
#define K_DIM   16
#define HALF_D  8
#define KNN     8
#define N_KEYS  256
#define D_IN    1024
#define H_DIM   128

// Global scratch
__device__ float    g_q[8192 * 32];                 // q: [T][32]
__device__ uint32_t g_W1sp[2 * H_DIM * D_IN];       // W1 tf32 2-split (t0, t1)

// ---------------------------------------------------------------------------
// tf32 helpers: a ~= t0 + t1 (11-bit mantissas); dropped t1*t1 ~ 2^-24
// ---------------------------------------------------------------------------
__device__ __forceinline__ uint32_t cvt_tf32(float a) {
    uint32_t u;
    asm("cvt.rna.tf32.f32 %0, %1;" : "=r"(u) : "f"(a));
    return u;
}
__device__ __forceinline__ void split2(float a, uint32_t& t0, uint32_t& t1) {
    t0 = cvt_tf32(a);
    t1 = cvt_tf32(a - __uint_as_float(t0));
}

__device__ __forceinline__ void mma_tf32(float* c, const uint32_t* a,
                                         const uint32_t* b) {
    asm volatile(
        "mma.sync.aligned.m16n8k8.row.col.f32.tf32.tf32.f32 "
        "{%0,%1,%2,%3}, {%4,%5,%6,%7}, {%8,%9}, {%0,%1,%2,%3};"
        : "+f"(c[0]), "+f"(c[1]), "+f"(c[2]), "+f"(c[3])
        : "r"(a[0]), "r"(a[1]), "r"(a[2]), "r"(a[3]), "r"(b[0]), "r"(b[1]));
}

// Packed fp32x2 FMA (Blackwell FFMA2): d.lo += a.lo*b.lo, d.hi += a.hi*b.hi
__device__ __forceinline__ void ffma2(unsigned long long& d,
                                      unsigned long long a,
                                      unsigned long long b) {
    asm("fma.rn.f32x2 %0, %1, %2, %0;" : "+l"(d) : "l"(a), "l"(b));
}
__device__ __forceinline__ float pair_sum(unsigned long long p) {
    return __uint_as_float((uint32_t)p) + __uint_as_float((uint32_t)(p >> 32));
}

// ---------------------------------------------------------------------------
// Kernel 0: pre-split W1 [128][1024] f32 -> g_W1sp[2][128][1024] tf32-as-u32
// ---------------------------------------------------------------------------
__global__ void split_w1_kernel(const float* __restrict__ W1) {
    int idx4 = blockIdx.x * 256 + threadIdx.x;    // over 32768 float4
    float4 v = ((const float4*)W1)[idx4];
    uint4 t0, t1;
    split2(v.x, t0.x, t1.x);
    split2(v.y, t0.y, t1.y);
    split2(v.z, t0.z, t1.z);
    split2(v.w, t0.w, t1.w);
    ((uint4*)g_W1sp)[idx4]         = t0;
    ((uint4*)g_W1sp)[32768 + idx4] = t1;
}

// ---------------------------------------------------------------------------
// GEMM kernel: hybrid tensor+SIMT.
//   k in [0,512):    tf32 2-split mma.sync (tensor pipe, instr-rate-limited)
//   k in [512,1024): fp32 FFMA2 SIMT (fma pipe), exact fp32 FMA chains
// Warps with wm=0 run HMMA->SIMT; wm=1 run SIMT->HMMA so each SMSP always
// has one warp feeding each pipe.
//
// RZ note: all tensor products for a 32-K chunk chain into a zero-init C
// (dm) and are drained into accm with RN adds.
//
// smem (bytes):
//   [0,512) b1s; [512,640) b2s
//   A_h: [1024,   +2*18432)  2 stages x 2 splits x 64 x 144B
//   B_h: [37888,  +2*36864)  2 stages x 2 splits x 128 x 144B
//   A_s: [111616, +2*9216)   2 stages x 64 x 144B (fp32 x)
//   B_s: [130048, +2*18432)  2 stages x 128 x 144B (fp32 W1)
//   W2:  [166912, +33792)    2 splits x 32 x 528B
//   A2 union after GEMM1: [1024, +67584)
// ---------------------------------------------------------------------------
#define ASPL     9216      // 64*144
#define BSPL     18432     // 128*144
#define AST      18432     // A_h stage stride = 2*ASPL
#define BST      36864     // B_h stage stride = 2*BSPL
#define SM_AS0   1024
#define SM_BS0   37888
#define SM_XS0   111616    // A_s base (stage stride ASPL)
#define SM_WS0   130048    // B_s base (stage stride BSPL)
#define SM_W2    166912
#define W2SPL    16896     // 32*528
#define SM_A2    1024
#define A2SPL    33792     // 64*528
#define SMEM_GEMM_BYTES 200704

__global__ __launch_bounds__(256, 1)
void gemm_kernel(const float* __restrict__ x, const float* __restrict__ W1,
                 const float* __restrict__ b1, const float* __restrict__ W2,
                 const float* __restrict__ b2)
{
    extern __shared__ char sm[];
    float* b1s = (float*)(sm);
    float* b2s = (float*)(sm + 512);

    const int tid  = threadIdx.x;
    const int lane = tid & 31;
    const int warp = tid >> 5;
    const int g    = lane >> 2;      // fragment group row
    const int tig  = lane & 3;       // thread-in-group
    const int wm   = warp >> 2;      // 0..1 (m)
    const int wn   = warp & 3;       // 0..3 (n)
    const int t0b  = blockIdx.x * 64;

    if (tid < 128) b1s[tid] = b1[tid];
    if (tid < 32)  b2s[tid] = b2[tid];

    // ---- W2 [32][128] -> tf32 split tiles ----
#pragma unroll
    for (int i = 0; i < 4; i++) {
        int idx4 = tid + i * 256;
        int n  = idx4 >> 5;
        int c4 = idx4 & 31;
        float4 v = *(const float4*)(W2 + n * H_DIM + c4 * 4);
        uint4 u0, u1;
        split2(v.x, u0.x, u1.x);
        split2(v.y, u0.y, u1.y);
        split2(v.z, u0.z, u1.z);
        split2(v.w, u0.w, u1.w);
        char* base = sm + SM_W2 + n * 528 + c4 * 16;
        *(uint4*)(base + 0 * W2SPL) = u0;
        *(uint4*)(base + 1 * W2SPL) = u1;
    }

    // ---- load geometry ----
    const float* xp[2];            // HMMA x (k<512)
    const float* xsp[2];           // SIMT x (k>=512)
    uint32_t sxa_off[2];
#pragma unroll
    for (int i = 0; i < 2; i++) {
        int r = (tid >> 3) + i * 32;   // 0..63
        int c = tid & 7;               // float4 col
        xp[i]      = x + (size_t)(t0b + r) * D_IN + c * 4;
        xsp[i]     = x + (size_t)(t0b + r) * D_IN + 512 + c * 4;
        sxa_off[i] = (uint32_t)(r * 144 + c * 16);
    }
    const uint32_t* wp[8];         // HMMA W1 splits
    uint32_t swb_off[8];
#pragma unroll
    for (int i = 0; i < 8; i++) {
        int idx = tid + i * 256;
        int s = idx >> 10, rem = idx & 1023;
        int r = rem >> 3, c = rem & 7;
        wp[i]      = g_W1sp + s * (H_DIM * D_IN) + r * D_IN + c * 4;
        swb_off[i] = (uint32_t)(s * BSPL + r * 144 + c * 16);
    }
    const float* wsp[4];           // SIMT W1 raw fp32 (k>=512)
    uint32_t sws_off[4];
#pragma unroll
    for (int i = 0; i < 4; i++) {
        int idx = tid + i * 256;       // 0..1023 over 128 rows x 8 f4
        int r = idx >> 3, c = idx & 7;
        wsp[i]     = W1 + (size_t)r * D_IN + 512 + c * 4;
        sws_off[i] = (uint32_t)(r * 144 + c * 16);
    }

    // ---- fragment / SIMT byte offsets ----
    uint32_t a_off[2];
#pragma unroll
    for (int mt = 0; mt < 2; mt++)
        a_off[mt] = (uint32_t)((wm * 32 + mt * 16 + g) * 144 + tig * 4);
    uint32_t b_off[4];
#pragma unroll
    for (int nt = 0; nt < 4; nt++)
        b_off[nt] = (uint32_t)((wn * 32 + nt * 8 + g) * 144 + tig * 4);
    uint32_t woff8[8];             // SIMT col byte offsets
#pragma unroll
    for (int c8 = 0; c8 < 8; c8++) {
        int col = wn * 32 + (c8 >> 1) * 8 + tig * 2 + (c8 & 1);
        woff8[c8] = (uint32_t)(col * 144);
    }
    uint32_t roff[2][2];           // SIMT row offsets [mt][jj]
#pragma unroll
    for (int mt = 0; mt < 2; mt++)
#pragma unroll
        for (int jj = 0; jj < 2; jj++)
            roff[mt][jj] = (uint32_t)((wm * 32 + mt * 16 + g + 8 * jj) * 144);

    float4 xa[2], xsa[2], wsa[4];
    uint4  wb[8];
#pragma unroll
    for (int i = 0; i < 2; i++) { xa[i] = *(const float4*)xp[i]; xsa[i] = *(const float4*)xsp[i]; }
#pragma unroll
    for (int i = 0; i < 8; i++) wb[i] = *(const uint4*)wp[i];
#pragma unroll
    for (int i = 0; i < 4; i++) wsa[i] = *(const float4*)wsp[i];

    float accm[2][4][4];
#pragma unroll
    for (int mt = 0; mt < 2; mt++)
#pragma unroll
        for (int nt = 0; nt < 4; nt++)
#pragma unroll
            for (int e = 0; e < 4; e++) accm[mt][nt][e] = 0.0f;

    // ---- prologue: store chunk 0 into stage 0 ----
    {
#pragma unroll
        for (int i = 0; i < 2; i++) {
            uint4 u0, u1;
            split2(xa[i].x, u0.x, u1.x);
            split2(xa[i].y, u0.y, u1.y);
            split2(xa[i].z, u0.z, u1.z);
            split2(xa[i].w, u0.w, u1.w);
            char* ba = sm + SM_AS0 + sxa_off[i];
            *(uint4*)(ba)        = u0;
            *(uint4*)(ba + ASPL) = u1;
            *(float4*)(sm + SM_XS0 + sxa_off[i]) = xsa[i];
        }
#pragma unroll
        for (int i = 0; i < 8; i++)
            *(uint4*)(sm + SM_BS0 + swb_off[i]) = wb[i];
#pragma unroll
        for (int i = 0; i < 4; i++)
            *(float4*)(sm + SM_WS0 + sws_off[i]) = wsa[i];
    }
    __syncthreads();

    // ---- mainloop: 16 chunks of 32 HMMA-k + 32 SIMT-k, double-buffered ----
    for (int ch = 0; ch < 16; ch++) {
        const int st = ch & 1;
        const char* a_stage = sm + SM_AS0 + st * AST;
        const char* b_stage = sm + SM_BS0 + st * BST;
        const char* as_st   = sm + SM_XS0 + st * ASPL;
        const char* ws_st   = sm + SM_WS0 + st * BSPL;

        if (ch < 15) {
#pragma unroll
            for (int i = 0; i < 2; i++) {
                xa[i]  = *(const float4*)(xp[i] + (ch + 1) * 32);
                xsa[i] = *(const float4*)(xsp[i] + (ch + 1) * 32);
            }
#pragma unroll
            for (int i = 0; i < 8; i++)
                wb[i] = *(const uint4*)(wp[i] + (ch + 1) * 32);
#pragma unroll
            for (int i = 0; i < 4; i++)
                wsa[i] = *(const float4*)(wsp[i] + (ch + 1) * 32);
        }

        auto do_hmma = [&]() {
            float dm[2][4][4];
#pragma unroll
            for (int mt = 0; mt < 2; mt++)
#pragma unroll
                for (int nt = 0; nt < 4; nt++)
#pragma unroll
                    for (int e = 0; e < 4; e++) dm[mt][nt][e] = 0.0f;
#pragma unroll
            for (int ks = 0; ks < 4; ks++) {
                const uint32_t kso = (uint32_t)ks * 32;
                uint32_t bf[2][4][2];
#pragma unroll
                for (int s = 0; s < 2; s++)
#pragma unroll
                    for (int nt = 0; nt < 4; nt++) {
                        const char* bb = b_stage + s * BSPL + b_off[nt] + kso;
                        bf[s][nt][0] = *(const uint32_t*)(bb);
                        bf[s][nt][1] = *(const uint32_t*)(bb + 16);
                    }
                uint32_t af[2][2][4];
#pragma unroll
                for (int s = 0; s < 2; s++)
#pragma unroll
                    for (int mt = 0; mt < 2; mt++) {
                        const char* ab = a_stage + s * ASPL + a_off[mt] + kso;
                        af[s][mt][0] = *(const uint32_t*)(ab);
                        af[s][mt][1] = *(const uint32_t*)(ab + 1152);
                        af[s][mt][2] = *(const uint32_t*)(ab + 16);
                        af[s][mt][3] = *(const uint32_t*)(ab + 1168);
                    }
#pragma unroll
                for (int mt = 0; mt < 2; mt++)
#pragma unroll
                    for (int nt = 0; nt < 4; nt++) {
                        mma_tf32(dm[mt][nt], af[0][mt], bf[0][nt]);  // T0
                        mma_tf32(dm[mt][nt], af[0][mt], bf[1][nt]);  // A0*B1
                        mma_tf32(dm[mt][nt], af[1][mt], bf[0][nt]);  // A1*B0
                    }
            }
#pragma unroll
            for (int mt = 0; mt < 2; mt++)
#pragma unroll
                for (int nt = 0; nt < 4; nt++)
#pragma unroll
                    for (int e = 0; e < 4; e++)
                        accm[mt][nt][e] += dm[mt][nt][e];
        };

        auto do_simt = [&]() {
#pragma unroll
            for (int mt = 0; mt < 2; mt++) {
                unsigned long long pacc[2][8];
#pragma unroll
                for (int jj = 0; jj < 2; jj++)
#pragma unroll
                    for (int c8 = 0; c8 < 8; c8++) pacc[jj][c8] = 0ull;
#pragma unroll
                for (int k4 = 0; k4 < 8; k4++) {
                    const uint32_t ko = (uint32_t)k4 * 16;
                    ulonglong2 xv0 = *(const ulonglong2*)(as_st + roff[mt][0] + ko);
                    ulonglong2 xv1 = *(const ulonglong2*)(as_st + roff[mt][1] + ko);
#pragma unroll
                    for (int c8 = 0; c8 < 8; c8++) {
                        ulonglong2 wv = *(const ulonglong2*)(ws_st + woff8[c8] + ko);
                        ffma2(pacc[0][c8], xv0.x, wv.x);
                        ffma2(pacc[0][c8], xv0.y, wv.y);
                        ffma2(pacc[1][c8], xv1.x, wv.x);
                        ffma2(pacc[1][c8], xv1.y, wv.y);
                    }
                }
#pragma unroll
                for (int nt = 0; nt < 4; nt++)
#pragma unroll
                    for (int e = 0; e < 4; e++)
                        accm[mt][nt][e] +=
                            pair_sum(pacc[e >> 1][nt * 2 + (e & 1)]);
            }
        };

        if (wm == 0) { do_hmma(); do_simt(); }
        else         { do_simt(); do_hmma(); }

        if (ch < 15) {
            const int nst = st ^ 1;
#pragma unroll
            for (int i = 0; i < 2; i++) {
                uint4 u0, u1;
                split2(xa[i].x, u0.x, u1.x);
                split2(xa[i].y, u0.y, u1.y);
                split2(xa[i].z, u0.z, u1.z);
                split2(xa[i].w, u0.w, u1.w);
                char* ba = sm + SM_AS0 + nst * AST + sxa_off[i];
                *(uint4*)(ba)        = u0;
                *(uint4*)(ba + ASPL) = u1;
                *(float4*)(sm + SM_XS0 + nst * ASPL + sxa_off[i]) = xsa[i];
            }
#pragma unroll
            for (int i = 0; i < 8; i++)
                *(uint4*)(sm + SM_BS0 + nst * BST + swb_off[i]) = wb[i];
#pragma unroll
            for (int i = 0; i < 4; i++)
                *(float4*)(sm + SM_WS0 + nst * BSPL + sws_off[i]) = wsa[i];
        }
        __syncthreads();
    }

    // ---- epilogue 1: h = relu(accm + b1) -> tf32 split into A2 tiles ----
#pragma unroll
    for (int mt = 0; mt < 2; mt++) {
        int r0 = wm * 32 + mt * 16 + g;
#pragma unroll
        for (int nt = 0; nt < 4; nt++) {
            int c0i = wn * 32 + nt * 8 + tig * 2;
            float h00 = fmaxf(accm[mt][nt][0] + b1s[c0i], 0.0f);
            float h01 = fmaxf(accm[mt][nt][1] + b1s[c0i + 1], 0.0f);
            float h10 = fmaxf(accm[mt][nt][2] + b1s[c0i], 0.0f);
            float h11 = fmaxf(accm[mt][nt][3] + b1s[c0i + 1], 0.0f);
            uint2 p0, p1;
            split2(h00, p0.x, p1.x);
            split2(h01, p0.y, p1.y);
            char* ba = sm + SM_A2 + r0 * 528 + c0i * 4;
            *(uint2*)(ba + 0 * A2SPL) = p0;
            *(uint2*)(ba + 1 * A2SPL) = p1;
            split2(h10, p0.x, p1.x);
            split2(h11, p0.y, p1.y);
            char* bb = sm + SM_A2 + (r0 + 8) * 528 + c0i * 4;
            *(uint2*)(bb + 0 * A2SPL) = p0;
            *(uint2*)(bb + 1 * A2SPL) = p1;
        }
    }
    __syncthreads();

    // ---- GEMM2: q = h @ W2^T (warp tile m32 x n8, K=128, 16 k8-steps) ----
    float accm2[2][4];
#pragma unroll
    for (int mt = 0; mt < 2; mt++)
#pragma unroll
        for (int e = 0; e < 4; e++) accm2[mt][e] = 0.0f;

    uint32_t a2_off[2];
#pragma unroll
    for (int mt = 0; mt < 2; mt++)
        a2_off[mt] = (uint32_t)((wm * 32 + mt * 16 + g) * 528 + tig * 4);
    const uint32_t w2_off = (uint32_t)((wn * 8 + g) * 528 + tig * 4);

#pragma unroll
    for (int ks = 0; ks < 16; ks++) {
        const uint32_t kso = (uint32_t)ks * 32;
        uint32_t bf[2][2];
#pragma unroll
        for (int s = 0; s < 2; s++) {
            const char* bb = sm + SM_W2 + s * W2SPL + w2_off + kso;
            bf[s][0] = *(const uint32_t*)(bb);
            bf[s][1] = *(const uint32_t*)(bb + 16);
        }
        float d2[2][4];
#pragma unroll
        for (int mt = 0; mt < 2; mt++)
#pragma unroll
            for (int e = 0; e < 4; e++) d2[mt][e] = 0.0f;

#pragma unroll
        for (int mt = 0; mt < 2; mt++) {
            uint32_t af0[4], af1[4];
            const char* ab0 = sm + SM_A2 + 0 * A2SPL + a2_off[mt] + kso;
            const char* ab1 = sm + SM_A2 + 1 * A2SPL + a2_off[mt] + kso;
            af0[0] = *(const uint32_t*)(ab0);
            af0[1] = *(const uint32_t*)(ab0 + 4224);
            af0[2] = *(const uint32_t*)(ab0 + 16);
            af0[3] = *(const uint32_t*)(ab0 + 4240);
            af1[0] = *(const uint32_t*)(ab1);
            af1[1] = *(const uint32_t*)(ab1 + 4224);
            af1[2] = *(const uint32_t*)(ab1 + 16);
            af1[3] = *(const uint32_t*)(ab1 + 4240);
            mma_tf32(d2[mt], af0, bf[0]);   // T0
            mma_tf32(d2[mt], af0, bf[1]);   // A0*B1
            mma_tf32(d2[mt], af1, bf[0]);   // A1*B0
        }
#pragma unroll
        for (int mt = 0; mt < 2; mt++)
#pragma unroll
            for (int e = 0; e < 4; e++) accm2[mt][e] += d2[mt][e];
    }

    // ---- epilogue 2: q + b2 -> global ----
#pragma unroll
    for (int mt = 0; mt < 2; mt++) {
        int r0  = t0b + wm * 32 + mt * 16 + g;
        int c0i = wn * 8 + tig * 2;
        float2 v0 = make_float2(accm2[mt][0] + b2s[c0i],
                                accm2[mt][1] + b2s[c0i + 1]);
        float2 v1 = make_float2(accm2[mt][2] + b2s[c0i],
                                accm2[mt][3] + b2s[c0i + 1]);
        *(float2*)&g_q[(size_t)r0 * 32 + c0i]       = v0;
        *(float2*)&g_q[(size_t)(r0 + 8) * 32 + c0i] = v1;
    }
}

// ===========================================================================
// Selection + gather kernel (proven logic, unchanged)
// ===========================================================================
__device__ __forceinline__ unsigned fmap(float f) {
    unsigned u = __float_as_uint(f);
    return (u & 0x80000000u) ? ~u : (u | 0x80000000u);
}
__device__ __forceinline__ float funmap(unsigned m) {
    return (m & 0x80000000u) ? __uint_as_float(m & 0x7FFFFFFFu)
                             : __uint_as_float(~m);
}

__device__ __forceinline__ void topk8_256(float sv[8], int lane,
                                          float* top_s, int* top_i) {
    for (int k = 0; k < KNN; k++) {
        float best = sv[0];
        int bj = 0;
#pragma unroll
        for (int j = 1; j < 8; j++) {
            if (sv[j] > best) { best = sv[j]; bj = j; }
        }
        unsigned u = fmap(best);
        unsigned g = __reduce_max_sync(0xFFFFFFFFu, u);
        unsigned cand = (u == g) ? (unsigned)(lane + 32 * bj) : 0xFFFFFFFFu;
        unsigned nw = __reduce_min_sync(0xFFFFFFFFu, cand);
        if (lane == (int)(nw & 31u)) {
            int jw = (int)(nw >> 5);
#pragma unroll
            for (int j = 0; j < 8; j++) {
                if (j == jw) sv[j] = -FLT_MAX;
            }
        }
        if (lane == 0) { top_s[k] = funmap(g); top_i[k] = (int)nw; }
    }
}

#define TPB2 16   // tokens per block

__global__ __launch_bounds__(256, 4)
void select_gather_kernel(const float* __restrict__ keys,
                          const float* __restrict__ values,
                          float* __restrict__ out)
{
    __shared__ float keysb[1024 * 9];
    __shared__ float wss[TPB2 * 16];
    __shared__ int   idxs[TPB2 * 16];
    __shared__ float top_s[8 * 2 * 8];
    __shared__ int   top_i[8 * 2 * 8];

    const int tid  = threadIdx.x;
    const int lane = tid & 31;
    const int warp = tid >> 5;
    const int t0   = blockIdx.x * TPB2;

    for (int e = tid; e < HEADS * 2 * N_KEYS * HALF_D; e += 256) {
        keysb[(e >> 3) * 9 + (e & 7)] = keys[e];
    }
    __syncthreads();

    for (int it = 0; it < 4; it++) {
        const int task = it * 8 + warp;
        const int tl = task >> 1;
        const int h  = task & 1;
        const int t  = t0 + tl;

        float q1r[8], q2r[8];
        const float* qrow = &g_q[(size_t)t * 32 + h * 16];
#pragma unroll
        for (int c = 0; c < 8; c++) {
            q1r[c] = __ldg(qrow + c);
            q2r[c] = __ldg(qrow + 8 + c);
        }

        float s1v[8], s2v[8];
        const float* k1 = &keysb[(h * 2 + 0) * N_KEYS * 9];
        const float* k2 = &keysb[(h * 2 + 1) * N_KEYS * 9];
#pragma unroll
        for (int j = 0; j < 8; j++) {
            const int n = lane + 32 * j;
            const float* kr1 = k1 + n * 9;
            const float* kr2 = k2 + n * 9;
            float a1 = 0.0f, a2 = 0.0f;
#pragma unroll
            for (int c = 0; c < 8; c++) {
                a1 += q1r[c] * kr1[c];
                a2 += q2r[c] * kr2[c];
            }
            s1v[j] = a1;
            s2v[j] = a2;
        }

        float* ts1 = &top_s[(warp * 2 + 0) * 8];
        float* ts2 = &top_s[(warp * 2 + 1) * 8];
        int*   ti1 = &top_i[(warp * 2 + 0) * 8];
        int*   ti2 = &top_i[(warp * 2 + 1) * 8];
        topk8_256(s1v, lane, ts1, ti1);
        topk8_256(s2v, lane, ts2, ti2);
        __syncwarp();

        const int a  = lane >> 2;
        const int b0 = (2 * lane) & 7;
        float cv0 = ts1[a] + ts2[b0];
        float cv1 = ts1[a] + ts2[b0 + 1];

        float ek[KNN];
        int   iks[KNN];
        float v0 = 0.0f, esum = 0.0f;
#pragma unroll
        for (int k = 0; k < KNN; k++) {
            float best;
            int slot;
            if (cv1 > cv0) { best = cv1; slot = 1; }
            else           { best = cv0; slot = 0; }
            unsigned u = fmap(best);
            unsigned g = __reduce_max_sync(0xFFFFFFFFu, u);
            unsigned cand = (u == g) ? (unsigned)(2 * lane + slot) : 0xFFFFFFFFu;
            unsigned jw = __reduce_min_sync(0xFFFFFFFFu, cand);
            float val = funmap(g);
            if (k == 0) v0 = val;
            float e = expf(val - v0);
            esum += e;
            if (lane == (int)(jw >> 1)) {
                if (jw & 1u) cv1 = -FLT_MAX;
                else         cv0 = -FLT_MAX;
            }
            if (lane == 0) {
                int aa = (int)(jw >> 3);
                int bb = (int)(jw & 7u);
                ek[k]  = e;
                iks[k] = ti1[aa] * N_KEYS + ti2[bb];
            }
        }
        if (lane == 0) {
#pragma unroll
            for (int k = 0; k < KNN; k++) {
                wss[tl * 16 + h * 8 + k]  = ek[k] / esum;
                idxs[tl * 16 + h * 8 + k] = iks[k];
            }
        }
        __syncwarp();
    }
    __syncthreads();

    const size_t c4 = (size_t)tid * 4;
    for (int tl = 0; tl < TPB2; tl++) {
        float4 acc = make_float4(0.0f, 0.0f, 0.0f, 0.0f);
#pragma unroll
        for (int k = 0; k < 16; k++) {
            const float wk = wss[tl * 16 + k];
            const int row  = idxs[tl * 16 + k];
            const float4 v = *reinterpret_cast<const float4*>(
                &values[((size_t)row << 10) + c4]);
            acc.x += wk * v.x;
            acc.y += wk * v.y;
            acc.z += wk * v.z;
            acc.w += wk * v.w;
        }
        *reinterpret_cast<float4*>(&out[((size_t)(t0 + tl) << 10) + c4]) = acc;
    }
}

// ===========================================================================
// Launch
// ===========================================================================
extern "C" void kernel_launch(void* const* d_in, const int* in_sizes, int n_in,
                              void* d_out, int out_size) {
    const float* x      = (const float*)d_in[0];
    const float* W1     = (const float*)d_in[1];
    const float* b1     = (const float*)d_in[2];
    const float* W2     = (const float*)d_in[3];
    const float* b2     = (const float*)d_in[4];
    const float* keys   = (const float*)d_in[5];
    const float* values = (const float*)d_in[6];
    float* out = (float*)d_out;

    const int T = in_sizes[0] / D_IN;   // 8192

    cudaFuncSetAttribute(gemm_kernel,
                         cudaFuncAttributeMaxDynamicSharedMemorySize,
                         SMEM_GEMM_BYTES);

    split_w1_kernel<<<H_DIM * D_IN / 4 / 256, 256>>>(W1);
    gemm_kernel<<<T / 64, 256, SMEM_GEMM_BYTES>>>(x, W1, b1, W2, b2);
    select_gather_kernel<<<T / TPB2, 256>>>(keys, values, out);
}

// round 11
// speedup vs baseline: 1.1023x; 1.1023x over previous
#include <cuda_runtime.h>
#include <cuda_bf16.h>
#include <math.h>
#include <float.h>
#include <stdint.h>

// Problem constants
#define HEADS   2
#define K_DIM   16
#define HALF_D  8
#define KNN     8
#define N_KEYS  256
#define D_IN    1024
#define H_DIM   128

// Global scratch
__device__ float    g_q[8192 * 32];                 // q: [T][32]
__device__ uint32_t g_W1sp[2 * H_DIM * D_IN];       // W1 tf32 2-split (t0, t1)

// ---------------------------------------------------------------------------
// tf32 helpers: a ~= t0 + t1 (11-bit mantissas); dropped t1*t1 ~ 2^-24
// ---------------------------------------------------------------------------
__device__ __forceinline__ uint32_t cvt_tf32(float a) {
    uint32_t u;
    asm("cvt.rna.tf32.f32 %0, %1;" : "=r"(u) : "f"(a));
    return u;
}
__device__ __forceinline__ void split2(float a, uint32_t& t0, uint32_t& t1) {
    t0 = cvt_tf32(a);
    t1 = cvt_tf32(a - __uint_as_float(t0));
}

__device__ __forceinline__ void mma_tf32(float* c, const uint32_t* a,
                                         const uint32_t* b) {
    asm volatile(
        "mma.sync.aligned.m16n8k8.row.col.f32.tf32.tf32.f32 "
        "{%0,%1,%2,%3}, {%4,%5,%6,%7}, {%8,%9}, {%0,%1,%2,%3};"
        : "+f"(c[0]), "+f"(c[1]), "+f"(c[2]), "+f"(c[3])
        : "r"(a[0]), "r"(a[1]), "r"(a[2]), "r"(a[3]), "r"(b[0]), "r"(b[1]));
}

// ---------------------------------------------------------------------------
// Kernel 0: pre-split W1 [128][1024] f32 -> g_W1sp[2][128][1024] tf32-as-u32
// ---------------------------------------------------------------------------
__global__ void split_w1_kernel(const float* __restrict__ W1) {
    int idx4 = blockIdx.x * 256 + threadIdx.x;    // over 32768 float4
    float4 v = ((const float4*)W1)[idx4];
    uint4 t0, t1;
    split2(v.x, t0.x, t1.x);
    split2(v.y, t0.y, t1.y);
    split2(v.z, t0.z, t1.z);
    split2(v.w, t0.w, t1.w);
    ((uint4*)g_W1sp)[idx4]         = t0;
    ((uint4*)g_W1sp)[32768 + idx4] = t1;
}

// ---------------------------------------------------------------------------
// GEMM kernel: q = relu(x @ W1^T + b1) @ W2^T + b2  via mma.sync tf32 (2-split)
// CTA = 64 tokens, 512 threads (16 warps: 4m x 4n), warp tile m16 x n32,
// BK = 32, double-buffered. 4 warps per SMSP to cover HMMA issue backpressure.
//
// RZ note: main term T0 = A0*B0 per-chunk zero-C (dm) drained with RN adds;
// correction terms A0*B1 + A1*B0 also go into dm (zero-C chain of 12 <=
// negligible RZ bias). Dropped A1*B1 ~ 2^-24.
//
// smem (bytes):
//   [0,512) b1s; [512,640) b2s
//   A stages: [1024, +2*18432)   2 stages x 2 splits x 64 rows x 144B
//   B stages: [37888, +2*36864)  2 stages x 2 splits x 128 rows x 144B
//   W2 tiles: [111616, +33792)   2 splits x 32 rows x 528B
//   A2 union: [1024, +67584)     2 splits x 64 rows x 528B (after GEMM1)
// ---------------------------------------------------------------------------
#define ASPL     9216      // 64*144
#define BSPL     18432     // 128*144
#define AST      18432     // stage stride A = 2*ASPL
#define BST      36864     // stage stride B = 2*BSPL
#define SM_AS0   1024
#define SM_BS0   37888
#define SM_W2    111616
#define W2SPL    16896     // 32*528
#define SM_A2    1024
#define A2SPL    33792     // 64*528
#define SMEM_GEMM_BYTES 145408

__global__ __launch_bounds__(512, 1)
void gemm_kernel(const float* __restrict__ x, const float* __restrict__ b1,
                 const float* __restrict__ W2, const float* __restrict__ b2)
{
    extern __shared__ char sm[];
    float* b1s = (float*)(sm);
    float* b2s = (float*)(sm + 512);

    const int tid  = threadIdx.x;
    const int lane = tid & 31;
    const int warp = tid >> 5;       // 0..15
    const int g    = lane >> 2;      // fragment group row
    const int tig  = lane & 3;       // thread-in-group
    const int wm   = warp >> 2;      // 0..3 (m)
    const int wn   = warp & 3;       // 0..3 (n)
    const int t0b  = blockIdx.x * 64;

    if (tid < 128) b1s[tid] = b1[tid];
    if (tid < 32)  b2s[tid] = b2[tid];

    // ---- W2 [32][128] -> tf32 split tiles W2s[2][32][132] ----
#pragma unroll
    for (int i = 0; i < 2; i++) {
        int idx4 = tid + i * 512;          // 1024 float4
        int n  = idx4 >> 5;
        int c4 = idx4 & 31;
        float4 v = *(const float4*)(W2 + n * H_DIM + c4 * 4);
        uint4 u0, u1;
        split2(v.x, u0.x, u1.x);
        split2(v.y, u0.y, u1.y);
        split2(v.z, u0.z, u1.z);
        split2(v.w, u0.w, u1.w);
        char* base = sm + SM_W2 + n * 528 + c4 * 16;
        *(uint4*)(base + 0 * W2SPL) = u0;
        *(uint4*)(base + 1 * W2SPL) = u1;
    }

    // ---- load geometry ----
    // A: 64 rows x 8 float4 = 512 -> exactly 1 per thread
    const int ar = tid >> 3;           // 0..63
    const int ac = tid & 7;            // 0..7
    const float* xp = x + (size_t)(t0b + ar) * D_IN + ac * 4;
    const uint32_t sxa_off = (uint32_t)(ar * 144 + ac * 16);

    // B: 2 splits x 128 rows x 8 float4 = 2048 -> 4 per thread
    const uint32_t* wp[4];
    uint32_t swb_off[4];
#pragma unroll
    for (int i = 0; i < 4; i++) {
        int idx = tid + i * 512;
        int s = idx >> 10, rem = idx & 1023;
        int r = rem >> 3, c = rem & 7;
        wp[i]      = g_W1sp + s * (H_DIM * D_IN) + r * D_IN + c * 4;
        swb_off[i] = (uint32_t)(s * BSPL + r * 144 + c * 16);
    }

    // ---- fragment byte offsets ----
    const uint32_t a_off = (uint32_t)((wm * 16 + g) * 144 + tig * 4);
    uint32_t b_off[4];
#pragma unroll
    for (int nt = 0; nt < 4; nt++)
        b_off[nt] = (uint32_t)((wn * 32 + nt * 8 + g) * 144 + tig * 4);

    float4 xa;
    uint4  wb[4];
    xa = *(const float4*)xp;
#pragma unroll
    for (int i = 0; i < 4; i++) wb[i] = *(const uint4*)wp[i];

    float accm[4][4];
#pragma unroll
    for (int nt = 0; nt < 4; nt++)
#pragma unroll
        for (int e = 0; e < 4; e++) accm[nt][e] = 0.0f;

    // ---- prologue: store chunk 0 into stage 0 ----
    {
        uint4 u0, u1;
        split2(xa.x, u0.x, u1.x);
        split2(xa.y, u0.y, u1.y);
        split2(xa.z, u0.z, u1.z);
        split2(xa.w, u0.w, u1.w);
        char* ba = sm + SM_AS0 + sxa_off;
        *(uint4*)(ba)        = u0;
        *(uint4*)(ba + ASPL) = u1;
#pragma unroll
        for (int i = 0; i < 4; i++)
            *(uint4*)(sm + SM_BS0 + swb_off[i]) = wb[i];
    }
    __syncthreads();

    // ---- mainloop: 32 K-chunks of 32, double-buffered ----
    for (int ch = 0; ch < 32; ch++) {
        const int st = ch & 1;
        const char* a_stage = sm + SM_AS0 + st * AST;
        const char* b_stage = sm + SM_BS0 + st * BST;

        if (ch < 31) {
            xa = *(const float4*)(xp + (ch + 1) * 32);
#pragma unroll
            for (int i = 0; i < 4; i++)
                wb[i] = *(const uint4*)(wp[i] + (ch + 1) * 32);
        }

        // per-chunk zero-C accumulator (RZ-bias protection)
        float dm[4][4];
#pragma unroll
        for (int nt = 0; nt < 4; nt++)
#pragma unroll
            for (int e = 0; e < 4; e++) dm[nt][e] = 0.0f;

#pragma unroll
        for (int ks = 0; ks < 4; ks++) {
            const uint32_t kso = (uint32_t)ks * 32;   // 8 cols * 4B
            uint32_t bf[2][4][2];
#pragma unroll
            for (int s = 0; s < 2; s++)
#pragma unroll
                for (int nt = 0; nt < 4; nt++) {
                    const char* bb = b_stage + s * BSPL + b_off[nt] + kso;
                    bf[s][nt][0] = *(const uint32_t*)(bb);
                    bf[s][nt][1] = *(const uint32_t*)(bb + 16);
                }
            uint32_t af[2][4];
#pragma unroll
            for (int s = 0; s < 2; s++) {
                const char* ab = a_stage + s * ASPL + a_off + kso;
                af[s][0] = *(const uint32_t*)(ab);
                af[s][1] = *(const uint32_t*)(ab + 1152);  // row +8
                af[s][2] = *(const uint32_t*)(ab + 16);    // col +4
                af[s][3] = *(const uint32_t*)(ab + 1168);
            }
#pragma unroll
            for (int nt = 0; nt < 4; nt++) {
                mma_tf32(dm[nt], af[0], bf[0][nt]);  // T0
                mma_tf32(dm[nt], af[0], bf[1][nt]);  // A0*B1
                mma_tf32(dm[nt], af[1], bf[0][nt]);  // A1*B0
            }
        }
        // drain chunk sums with RN fp32 adds
#pragma unroll
        for (int nt = 0; nt < 4; nt++)
#pragma unroll
            for (int e = 0; e < 4; e++)
                accm[nt][e] += dm[nt][e];

        if (ch < 31) {
            const int nst = st ^ 1;
            uint4 u0, u1;
            split2(xa.x, u0.x, u1.x);
            split2(xa.y, u0.y, u1.y);
            split2(xa.z, u0.z, u1.z);
            split2(xa.w, u0.w, u1.w);
            char* ba = sm + SM_AS0 + nst * AST + sxa_off;
            *(uint4*)(ba)        = u0;
            *(uint4*)(ba + ASPL) = u1;
#pragma unroll
            for (int i = 0; i < 4; i++)
                *(uint4*)(sm + SM_BS0 + nst * BST + swb_off[i]) = wb[i];
        }
        __syncthreads();
    }

    // ---- epilogue 1: h = relu(accm + b1) -> tf32 split into A2 tiles ----
    {
        int r0 = wm * 16 + g;
#pragma unroll
        for (int nt = 0; nt < 4; nt++) {
            int c0i = wn * 32 + nt * 8 + tig * 2;
            float h00 = fmaxf(accm[nt][0] + b1s[c0i], 0.0f);
            float h01 = fmaxf(accm[nt][1] + b1s[c0i + 1], 0.0f);
            float h10 = fmaxf(accm[nt][2] + b1s[c0i], 0.0f);
            float h11 = fmaxf(accm[nt][3] + b1s[c0i + 1], 0.0f);
            uint2 p0, p1;
            split2(h00, p0.x, p1.x);
            split2(h01, p0.y, p1.y);
            char* ba = sm + SM_A2 + r0 * 528 + c0i * 4;
            *(uint2*)(ba + 0 * A2SPL) = p0;
            *(uint2*)(ba + 1 * A2SPL) = p1;
            split2(h10, p0.x, p1.x);
            split2(h11, p0.y, p1.y);
            char* bb = sm + SM_A2 + (r0 + 8) * 528 + c0i * 4;
            *(uint2*)(bb + 0 * A2SPL) = p0;
            *(uint2*)(bb + 1 * A2SPL) = p1;
        }
    }
    __syncthreads();

    // ---- GEMM2: q = h @ W2^T (warp tile m16 x n8, K=128, 16 k8-steps) ----
    float accm2[4];
#pragma unroll
    for (int e = 0; e < 4; e++) accm2[e] = 0.0f;

    const uint32_t a2_off = (uint32_t)((wm * 16 + g) * 528 + tig * 4);
    const uint32_t w2_off = (uint32_t)((wn * 8 + g) * 528 + tig * 4);

#pragma unroll
    for (int ks = 0; ks < 16; ks++) {
        const uint32_t kso = (uint32_t)ks * 32;
        uint32_t bf[2][2];
#pragma unroll
        for (int s = 0; s < 2; s++) {
            const char* bb = sm + SM_W2 + s * W2SPL + w2_off + kso;
            bf[s][0] = *(const uint32_t*)(bb);
            bf[s][1] = *(const uint32_t*)(bb + 16);
        }
        float d2[4];
#pragma unroll
        for (int e = 0; e < 4; e++) d2[e] = 0.0f;

        uint32_t af0[4], af1[4];
        const char* ab0 = sm + SM_A2 + 0 * A2SPL + a2_off + kso;
        const char* ab1 = sm + SM_A2 + 1 * A2SPL + a2_off + kso;
        af0[0] = *(const uint32_t*)(ab0);
        af0[1] = *(const uint32_t*)(ab0 + 4224);   // row +8 (stride 528)
        af0[2] = *(const uint32_t*)(ab0 + 16);
        af0[3] = *(const uint32_t*)(ab0 + 4240);
        af1[0] = *(const uint32_t*)(ab1);
        af1[1] = *(const uint32_t*)(ab1 + 4224);
        af1[2] = *(const uint32_t*)(ab1 + 16);
        af1[3] = *(const uint32_t*)(ab1 + 4240);
        mma_tf32(d2, af0, bf[0]);   // T0
        mma_tf32(d2, af0, bf[1]);   // A0*B1
        mma_tf32(d2, af1, bf[0]);   // A1*B0

#pragma unroll
        for (int e = 0; e < 4; e++) accm2[e] += d2[e];
    }

    // ---- epilogue 2: q + b2 -> global ----
    {
        int r0  = t0b + wm * 16 + g;
        int c0i = wn * 8 + tig * 2;
        float2 v0 = make_float2(accm2[0] + b2s[c0i],
                                accm2[1] + b2s[c0i + 1]);
        float2 v1 = make_float2(accm2[2] + b2s[c0i],
                                accm2[3] + b2s[c0i + 1]);
        *(float2*)&g_q[(size_t)r0 * 32 + c0i]       = v0;
        *(float2*)&g_q[(size_t)(r0 + 8) * 32 + c0i] = v1;
    }
}

// ===========================================================================
// Selection + gather kernel (proven logic, unchanged)
// ===========================================================================
__device__ __forceinline__ unsigned fmap(float f) {
    unsigned u = __float_as_uint(f);
    return (u & 0x80000000u) ? ~u : (u | 0x80000000u);
}
__device__ __forceinline__ float funmap(unsigned m) {
    return (m & 0x80000000u) ? __uint_as_float(m & 0x7FFFFFFFu)
                             : __uint_as_float(~m);
}

__device__ __forceinline__ void topk8_256(float sv[8], int lane,
                                          float* top_s, int* top_i) {
    for (int k = 0; k < KNN; k++) {
        float best = sv[0];
        int bj = 0;
#pragma unroll
        for (int j = 1; j < 8; j++) {
            if (sv[j] > best) { best = sv[j]; bj = j; }
        }
        unsigned u = fmap(best);
        unsigned g = __reduce_max_sync(0xFFFFFFFFu, u);
        unsigned cand = (u == g) ? (unsigned)(lane + 32 * bj) : 0xFFFFFFFFu;
        unsigned nw = __reduce_min_sync(0xFFFFFFFFu, cand);
        if (lane == (int)(nw & 31u)) {
            int jw = (int)(nw >> 5);
#pragma unroll
            for (int j = 0; j < 8; j++) {
                if (j == jw) sv[j] = -FLT_MAX;
            }
        }
        if (lane == 0) { top_s[k] = funmap(g); top_i[k] = (int)nw; }
    }
}

#define TPB2 16   // tokens per block

__global__ __launch_bounds__(256, 4)
void select_gather_kernel(const float* __restrict__ keys,
                          const float* __restrict__ values,
                          float* __restrict__ out)
{
    __shared__ float keysb[1024 * 9];
    __shared__ float wss[TPB2 * 16];
    __shared__ int   idxs[TPB2 * 16];
    __shared__ float top_s[8 * 2 * 8];
    __shared__ int   top_i[8 * 2 * 8];

    const int tid  = threadIdx.x;
    const int lane = tid & 31;
    const int warp = tid >> 5;
    const int t0   = blockIdx.x * TPB2;

    for (int e = tid; e < HEADS * 2 * N_KEYS * HALF_D; e += 256) {
        keysb[(e >> 3) * 9 + (e & 7)] = keys[e];
    }
    __syncthreads();

    for (int it = 0; it < 4; it++) {
        const int task = it * 8 + warp;
        const int tl = task >> 1;
        const int h  = task & 1;
        const int t  = t0 + tl;

        float q1r[8], q2r[8];
        const float* qrow = &g_q[(size_t)t * 32 + h * 16];
#pragma unroll
        for (int c = 0; c < 8; c++) {
            q1r[c] = __ldg(qrow + c);
            q2r[c] = __ldg(qrow + 8 + c);
        }

        float s1v[8], s2v[8];
        const float* k1 = &keysb[(h * 2 + 0) * N_KEYS * 9];
        const float* k2 = &keysb[(h * 2 + 1) * N_KEYS * 9];
#pragma unroll
        for (int j = 0; j < 8; j++) {
            const int n = lane + 32 * j;
            const float* kr1 = k1 + n * 9;
            const float* kr2 = k2 + n * 9;
            float a1 = 0.0f, a2 = 0.0f;
#pragma unroll
            for (int c = 0; c < 8; c++) {
                a1 += q1r[c] * kr1[c];
                a2 += q2r[c] * kr2[c];
            }
            s1v[j] = a1;
            s2v[j] = a2;
        }

        float* ts1 = &top_s[(warp * 2 + 0) * 8];
        float* ts2 = &top_s[(warp * 2 + 1) * 8];
        int*   ti1 = &top_i[(warp * 2 + 0) * 8];
        int*   ti2 = &top_i[(warp * 2 + 1) * 8];
        topk8_256(s1v, lane, ts1, ti1);
        topk8_256(s2v, lane, ts2, ti2);
        __syncwarp();

        const int a  = lane >> 2;
        const int b0 = (2 * lane) & 7;
        float cv0 = ts1[a] + ts2[b0];
        float cv1 = ts1[a] + ts2[b0 + 1];

        float ek[KNN];
        int   iks[KNN];
        float v0 = 0.0f, esum = 0.0f;
#pragma unroll
        for (int k = 0; k < KNN; k++) {
            float best;
            int slot;
            if (cv1 > cv0) { best = cv1; slot = 1; }
            else           { best = cv0; slot = 0; }
            unsigned u = fmap(best);
            unsigned g = __reduce_max_sync(0xFFFFFFFFu, u);
            unsigned cand = (u == g) ? (unsigned)(2 * lane + slot) : 0xFFFFFFFFu;
            unsigned jw = __reduce_min_sync(0xFFFFFFFFu, cand);
            float val = funmap(g);
            if (k == 0) v0 = val;
            float e = expf(val - v0);
            esum += e;
            if (lane == (int)(jw >> 1)) {
                if (jw & 1u) cv1 = -FLT_MAX;
                else         cv0 = -FLT_MAX;
            }
            if (lane == 0) {
                int aa = (int)(jw >> 3);
                int bb = (int)(jw & 7u);
                ek[k]  = e;
                iks[k] = ti1[aa] * N_KEYS + ti2[bb];
            }
        }
        if (lane == 0) {
#pragma unroll
            for (int k = 0; k < KNN; k++) {
                wss[tl * 16 + h * 8 + k]  = ek[k] / esum;
                idxs[tl * 16 + h * 8 + k] = iks[k];
            }
        }
        __syncwarp();
    }
    __syncthreads();

    const size_t c4 = (size_t)tid * 4;
    for (int tl = 0; tl < TPB2; tl++) {
        float4 acc = make_float4(0.0f, 0.0f, 0.0f, 0.0f);
#pragma unroll
        for (int k = 0; k < 16; k++) {
            const float wk = wss[tl * 16 + k];
            const int row  = idxs[tl * 16 + k];
            const float4 v = *reinterpret_cast<const float4*>(
                &values[((size_t)row << 10) + c4]);
            acc.x += wk * v.x;
            acc.y += wk * v.y;
            acc.z += wk * v.z;
            acc.w += wk * v.w;
        }
        *reinterpret_cast<float4*>(&out[((size_t)(t0 + tl) << 10) + c4]) = acc;
    }
}

// ===========================================================================
// Launch
// ===========================================================================
extern "C" void kernel_launch(void* const* d_in, const int* in_sizes, int n_in,
                              void* d_out, int out_size) {
    const float* x      = (const float*)d_in[0];
    const float* W1     = (const float*)d_in[1];
    const float* b1     = (const float*)d_in[2];
    const float* W2     = (const float*)d_in[3];
    const float* b2     = (const float*)d_in[4];
    const float* keys   = (const float*)d_in[5];
    const float* values = (const float*)d_in[6];
    float* out = (float*)d_out;

    const int T = in_sizes[0] / D_IN;   // 8192

    cudaFuncSetAttribute(gemm_kernel,
                         cudaFuncAttributeMaxDynamicSharedMemorySize,
                         SMEM_GEMM_BYTES);

    split_w1_kernel<<<H_DIM * D_IN / 4 / 256, 256>>>(W1);
    gemm_kernel<<<T / 64, 512, SMEM_GEMM_BYTES>>>(x, b1, W2, b2);
    select_gather_kernel<<<T / TPB2, 256>>>(keys, values, out);
}